// round 12
// baseline (speedup 1.0000x reference)
#include <cuda_runtime.h>
#include <cuda_bf16.h>
#include <cstdint>
#include <cstring>

#define CC 32
#define DD 48
#define HH 64
#define WW 208
#define HW 13312            // HH*WW
#define NELEM (CC*DD*HH*WW) // 20447232
#define CEPS 1e-5f
#define NEGINF -3.402823e38f

typedef unsigned long long ull;

// ---------- scratch (device globals: allocation-free) ----------
__device__ float g_kn[4 * 5 * HW];        // normalized guidance
__device__ float g_xt[NELEM];             // x transposed [d][h][w][c]
__device__ float g_accA[NELEM];           // W fwd
__device__ float g_accB[NELEM];           // W bwd
__device__ float g_accC[NELEM];           // H fwd
__device__ float g_accD[NELEM];           // H bwd
__device__ __nv_bfloat16 g_bh[NELEM];     // activation hi split [d][h][w][c]
__device__ __nv_bfloat16 g_bl[NELEM];     // activation lo split
__device__ uint32_t g_wfrag[2 * 27 * 512]; // B fragments [sp][tap][kt][nt][lane][reg]
__device__ float g_bias2[32];
__device__ float g_s1v[32];
__device__ float g_b1v[32];

// ---------- helpers ----------
__device__ __forceinline__ uint32_t smem_u32(const void* p) {
    uint32_t a;
    asm("{ .reg .u64 t; cvta.to.shared.u64 t, %1; cvt.u32.u64 %0, t; }" : "=r"(a) : "l"(p));
    return a;
}
__device__ __forceinline__ void ldm4(uint32_t* r, uint32_t addr) {
    asm volatile("ldmatrix.sync.aligned.m8n8.x4.shared.b16 {%0,%1,%2,%3}, [%4];"
                 : "=r"(r[0]), "=r"(r[1]), "=r"(r[2]), "=r"(r[3]) : "r"(addr));
}
__device__ __forceinline__ void mma16816(float* c, const uint32_t* a, uint32_t b0, uint32_t b1) {
    asm volatile("mma.sync.aligned.m16n8k16.row.col.f32.bf16.bf16.f32 "
                 "{%0,%1,%2,%3}, {%4,%5,%6,%7}, {%8,%9}, {%0,%1,%2,%3};"
                 : "+f"(c[0]), "+f"(c[1]), "+f"(c[2]), "+f"(c[3])
                 : "r"(a[0]), "r"(a[1]), "r"(a[2]), "r"(a[3]), "r"(b0), "r"(b1));
}
__device__ __forceinline__ unsigned short bf16bits(__nv_bfloat16 v) {
    unsigned short s;
    memcpy(&s, &v, 2);
    return s;
}
__device__ __forceinline__ void cpasync16(uint32_t d, const void* s, bool valid) {
    int sz = valid ? 16 : 0;
    asm volatile("cp.async.cg.shared.global [%0], [%1], 16, %2;"
                 :: "r"(d), "l"(s), "r"(sz) : "memory");
}
__device__ __forceinline__ void cpasync_commit_wait() {
    asm volatile("cp.async.commit_group;" ::: "memory");
    asm volatile("cp.async.wait_group 0;" ::: "memory");
}

// ---------- 1) guidance L1 normalization ----------
__global__ void k_norm(const float* __restrict__ g) {
    int i = blockIdx.x * blockDim.x + threadIdx.x;
    if (i >= 4 * HW) return;
    int dir = i / HW;
    int hw  = i % HW;
    float v[5];
    float s = 0.f;
#pragma unroll
    for (int j = 0; j < 5; j++) {
        v[j] = g[(5 * dir + j) * HW + hw];
        s += fabsf(v[j]);
    }
    float inv = 1.f / fmaxf(s, 1e-12f);
#pragma unroll
    for (int j = 0; j < 5; j++)
        g_kn[(dir * 5 + j) * HW + hw] = v[j] * inv;
}

// ---------- 2) transpose NCDHW -> [d][h][w][c] ----------
__global__ void k_transpose(const float* __restrict__ x) {
    __shared__ float t[32][209];
    int d = blockIdx.x / HH;
    int h = blockIdx.x % HH;
    for (int i = threadIdx.x; i < 32 * WW; i += blockDim.x) {
        int c = i / WW, w = i % WW;
        t[c][w] = x[((c * DD + d) * HH + h) * WW + w];
    }
    __syncthreads();
    float* dst = g_xt + (d * HH + h) * WW * 32;
    for (int i = threadIdx.x; i < WW * 32; i += blockDim.x) {
        dst[i] = t[i & 31][i >> 5];
    }
}

// ---------- 3) prep: BN params + bf16-split B fragments in mma frag order ----------
__global__ void k_wfrag(const float* __restrict__ cw,
                        const float* __restrict__ g1, const float* __restrict__ b1,
                        const float* __restrict__ m1, const float* __restrict__ v1,
                        const float* __restrict__ g2, const float* __restrict__ b2,
                        const float* __restrict__ m2, const float* __restrict__ v2) {
    int i = blockIdx.x * blockDim.x + threadIdx.x;
    if (i < 2 * 27 * 512) {
        int reg  = i & 1;
        int lane = (i >> 1) & 31;
        int nt   = (i >> 6) & 3;
        int kt   = (i >> 8) & 1;
        int rest = i >> 9;
        int tap  = rest % 27;
        int sp   = rest / 27;
        int oc   = nt * 8 + (lane >> 2);
        int icb  = kt * 16 + (lane & 3) * 2 + reg * 8;
        float s2 = g2[oc] * rsqrtf(v2[oc] + CEPS);
        uint32_t pack = 0;
#pragma unroll
        for (int e = 0; e < 2; e++) {
            int ic = icb + e;
            float wv = cw[(oc * 32 + ic) * 27 + tap] * s2;
            __nv_bfloat16 wh = __float2bfloat16(wv);
            __nv_bfloat16 val = sp ? __float2bfloat16(wv - __bfloat162float(wh)) : wh;
            pack |= (uint32_t)bf16bits(val) << (16 * e);
        }
        g_wfrag[i] = pack;
    }
    if (i < 32) {
        float s2 = g2[i] * rsqrtf(v2[i] + CEPS);
        g_bias2[i] = b2[i] - m2[i] * s2;
        float s1 = g1[i] * rsqrtf(v1[i] + CEPS);
        g_s1v[i] = s1;
        g_b1v[i] = b1[i] - m1[i] * s1;
    }
}

// ---------- 4) fused 4-direction scan: warp = 8 D-slices x 4 channels; 4352 warps ----------
// bx < 1024: W-scans (h=bx&63, dir=(bx>>6)&1, cg=bx>>7)
// bx >= 1024: H-scans (i=bx-1024: w=i%208, r=i/208, dir=r&1, cg=r>>1)
__global__ void __launch_bounds__(32) k_scan() {
    int lane = threadIdx.x;
    int ds = lane >> 2;                 // 0..7, 6 d's each
    int cl = lane & 3;
    int bx = blockIdx.x;

    int nsteps, pitch, p0;
    const float* kb; float* ob; int kpitch;
    int cg;
    int planeIdx0;
    if (bx < 1024) {
        int h = bx & 63;
        int dir = (bx >> 6) & 1;
        cg = bx >> 7;
        nsteps = WW;
        kb = g_kn + dir * 5 * HW + h * WW;
        ob = dir ? g_accB : g_accA;
        int ps = dir ? -1 : 1;
        p0 = dir ? (WW - 1) : 0;
        pitch = ps;
        kpitch = ps;
        planeIdx0 = h * WW + p0;
    } else {
        int i = bx - 1024;
        int w = i % 208;
        int r = i / 208;
        int dir = r & 1;
        cg = r >> 1;
        nsteps = HH;
        kb = g_kn + (2 + dir) * 5 * HW + w;
        ob = dir ? g_accD : g_accC;
        int hs = dir ? -1 : 1;
        int h0 = dir ? (HH - 1) : 0;
        pitch = hs * WW;
        kpitch = hs * WW;
        planeIdx0 = h0 * WW + w;
        p0 = h0 * WW;
    }
    int c = cg * 4 + cl;
    int d0 = ds * 6;

    const float* xp = g_xt + ((long long)d0 * HW + planeIdx0) * 32 + c;
    float* op = ob + ((long long)d0 * HW + planeIdx0) * 32 + c;
    const long long DSTR = (long long)HW * 32;
    const long long PSTR = (long long)pitch * 32;
    const float* kp;
    if (bx < 1024) kp = kb + ((pitch > 0) ? 0 : (WW - 1));
    else kp = kb + p0;

    float A[6], xv[6], wv[5];
    float lmx = NEGINF;
#pragma unroll
    for (int j = 0; j < 6; j++) {
        xv[j] = xp[j * DSTR];
        A[j] = xv[j];
        lmx = fmaxf(lmx, A[j]);
    }
#pragma unroll
    for (int j = 0; j < 5; j++) wv[j] = kp[j * HW];
    float gmx = fmaxf(lmx, __shfl_xor_sync(0xffffffffu, lmx, 4));
    gmx = fmaxf(gmx, __shfl_xor_sync(0xffffffffu, gmx, 8));
    gmx = fmaxf(gmx, __shfl_xor_sync(0xffffffffu, gmx, 16));

    for (int s = 0; s < nsteps; s++) {
        bool last = (s == nsteps - 1);
        const float* xpn = last ? xp : (xp + PSTR);
        const float* kpn = last ? kp : (kp + kpitch);
        float xn[6], wn[5];
#pragma unroll
        for (int j = 0; j < 6; j++) xn[j] = xpn[j * DSTR];
#pragma unroll
        for (int j = 0; j < 5; j++) wn[j] = kpn[j * HW];

        float fromUp = __shfl_up_sync(0xffffffffu, A[5], 4);
        float fromDn = __shfl_down_sync(0xffffffffu, A[0], 4);
        float up0   = (ds == 0) ? A[0] : fromUp;
        float dnTop = (ds == 7) ? A[5] : fromDn;
        float w0 = wv[0], w1 = wv[1], w2 = wv[2], w3 = wv[3], w4 = wv[4];
        float gterm = w4 * gmx;
        float prevOld = A[0];
#pragma unroll
        for (int j = 0; j < 6; j++) {
            float old = A[j];
            float up = (j == 0) ? up0 : prevOld;
            float dn = (j == 5) ? dnTop : A[j + 1];
            float nv = fmaf(w0, xv[j], fmaf(w1, old, fmaf(w2, up, fmaf(w3, dn, gterm))));
            op[j * DSTR] = nv;
            A[j] = nv;
            prevOld = old;
        }
        float t0 = fmaxf(A[0], A[1]);
        float t1 = fmaxf(A[2], A[3]);
        float t2 = fmaxf(A[4], A[5]);
        float lm = fmaxf(t0, fmaxf(t1, t2));
        lm = fmaxf(lm, __shfl_xor_sync(0xffffffffu, lm, 4));
        lm = fmaxf(lm, __shfl_xor_sync(0xffffffffu, lm, 8));
        gmx = fmaxf(lm, __shfl_xor_sync(0xffffffffu, lm, 16));

#pragma unroll
        for (int j = 0; j < 6; j++) xv[j] = xn[j];
#pragma unroll
        for (int j = 0; j < 5; j++) wv[j] = wn[j];
        xp = xpn;
        kp = kpn;
        op += PSTR;
    }
}

// ---------- 5) combine: relu(bn1(max4)) -> bf16 hi/lo splits, [d][h][w][c] ----------
__global__ void __launch_bounds__(256) k_combine() {
    __shared__ float s1s[32], b1s[32];
    int tid = threadIdx.x;
    if (tid < 32) { s1s[tid] = g_s1v[tid]; b1s[tid] = g_b1v[tid]; }
    __syncthreads();
    int i = blockIdx.x * 256 + tid;
    if (i >= NELEM / 4) return;
    float4 a = ((const float4*)g_accA)[i];
    float4 b = ((const float4*)g_accB)[i];
    float4 cc = ((const float4*)g_accC)[i];
    float4 dd = ((const float4*)g_accD)[i];
    int c0 = (i * 4) & 31;
    float v[4];
    v[0] = fmaxf(fmaxf(fmaxf(a.x, b.x), fmaxf(cc.x, dd.x)) * s1s[c0 + 0] + b1s[c0 + 0], 0.f);
    v[1] = fmaxf(fmaxf(fmaxf(a.y, b.y), fmaxf(cc.y, dd.y)) * s1s[c0 + 1] + b1s[c0 + 1], 0.f);
    v[2] = fmaxf(fmaxf(fmaxf(a.z, b.z), fmaxf(cc.z, dd.z)) * s1s[c0 + 2] + b1s[c0 + 2], 0.f);
    v[3] = fmaxf(fmaxf(fmaxf(a.w, b.w), fmaxf(cc.w, dd.w)) * s1s[c0 + 3] + b1s[c0 + 3], 0.f);
    uint32_t hp[2], lp[2];
#pragma unroll
    for (int j = 0; j < 2; j++) {
        __nv_bfloat16 h0 = __float2bfloat16(v[2 * j]);
        __nv_bfloat16 h1 = __float2bfloat16(v[2 * j + 1]);
        __nv_bfloat16 l0 = __float2bfloat16(v[2 * j] - __bfloat162float(h0));
        __nv_bfloat16 l1 = __float2bfloat16(v[2 * j + 1] - __bfloat162float(h1));
        hp[j] = (uint32_t)bf16bits(h0) | ((uint32_t)bf16bits(h1) << 16);
        lp[j] = (uint32_t)bf16bits(l0) | ((uint32_t)bf16bits(l1) << 16);
    }
    ((uint2*)g_bh)[i] = make_uint2(hp[0], hp[1]);
    ((uint2*)g_bl)[i] = make_uint2(lp[0], lp[1]);
}

// ---------- 6) conv via warp HMMA: 27 shifted GEMMs, 2-term split (R9 version) ----------
// CTA = M=128 w-rows (valid 104) x N=32 oc; 4 warps each m32 x n32.
// sAct rows padded to 40 bf16 (80B) -> conflict-free ldmatrix.
// B fragments via __ldg (110KB, L1-resident).
#define AROW 40
#define ASP_OFF (130 * AROW)            // bf16 elems per split
__global__ void __launch_bounds__(128) k_mma(const float* __restrict__ xres,
                                             float* __restrict__ out) {
    __shared__ alignas(16) __nv_bfloat16 sAct[2 * ASP_OFF];   // 20800 B
    __shared__ float sBias[32];

    int tid = threadIdx.x;
    int wid = tid >> 5;
    int lane = tid & 31;
    int h = blockIdx.x;
    int d = blockIdx.y;
    int w0 = blockIdx.z * 104;

    if (tid < 32) sBias[tid] = g_bias2[tid];

    uint32_t sact_u = smem_u32(sAct);
    uint32_t lm_lane = (uint32_t)((lane & 15) * (AROW * 2) + (lane >> 4) * 16);

    float acc[2][4][4];
#pragma unroll
    for (int mt = 0; mt < 2; mt++)
#pragma unroll
        for (int nt = 0; nt < 4; nt++)
#pragma unroll
            for (int r = 0; r < 4; r++) acc[mt][nt][r] = 0.f;

#pragma unroll
    for (int kd = 0; kd < 3; kd++) {
        int din = d + kd - 1;
        if ((unsigned)din >= DD) continue;
#pragma unroll
        for (int kh = 0; kh < 3; kh++) {
            int hin = h + kh - 1;
            if ((unsigned)hin >= HH) continue;

            __syncthreads();    // previous phase's reads complete
            // stage activations via cp.async: rows w0-1..w0+128 (130) x 32 bf16, hi+lo
            {
                long long rowb = (long long)(din * HH + hin) * WW;
                for (int c = tid; c < 1040; c += 128) {
                    int sp  = c / 520;
                    int rem = c - sp * 520;
                    int r = rem >> 2, q = rem & 3;
                    int w = w0 - 1 + r;
                    bool valid = (unsigned)w < WW;
                    int wc = valid ? w : 0;
                    const __nv_bfloat16* gs = (sp ? g_bl : g_bh) + (rowb + wc) * 32 + q * 8;
                    cpasync16(sact_u + (uint32_t)((sp * ASP_OFF + r * AROW) * 2 + q * 16),
                              gs, valid);
                }
            }
            cpasync_commit_wait();
            __syncthreads();

            int tap3 = kd * 9 + kh * 3;
#pragma unroll
            for (int kw = 0; kw < 3; kw++) {
                uint32_t Afr[2][2][2][4];       // [asp][mt][kt][4]
#pragma unroll
                for (int asp = 0; asp < 2; asp++)
#pragma unroll
                    for (int mt = 0; mt < 2; mt++)
#pragma unroll
                        for (int kt = 0; kt < 2; kt++) {
                            uint32_t addr = sact_u + (uint32_t)(asp * ASP_OFF * 2) + lm_lane
                                          + (uint32_t)((wid * 32 + mt * 16 + kw) * (AROW * 2)
                                                       + kt * 32);
                            ldm4(Afr[asp][mt][kt], addr);
                        }
                uint2 Bfr[2][2][4];             // [bsp][kt][nt]
#pragma unroll
                for (int bsp = 0; bsp < 2; bsp++) {
                    const uint2* wb = (const uint2*)(g_wfrag + (bsp * 27 + tap3 + kw) * 512);
#pragma unroll
                    for (int kt = 0; kt < 2; kt++)
#pragma unroll
                        for (int nt = 0; nt < 4; nt++)
                            Bfr[bsp][kt][nt] = __ldg(&wb[(kt * 4 + nt) * 32 + lane]);
                }
#pragma unroll
                for (int cb = 0; cb < 3; cb++) {        // (ah,bh), (ah,bl), (al,bh)
                    int asp = (cb == 2) ? 1 : 0;
                    int bsp = (cb == 1) ? 1 : 0;
#pragma unroll
                    for (int mt = 0; mt < 2; mt++)
#pragma unroll
                        for (int nt = 0; nt < 4; nt++)
#pragma unroll
                            for (int kt = 0; kt < 2; kt++)
                                mma16816(acc[mt][nt], Afr[asp][mt][kt],
                                         Bfr[bsp][kt][nt].x, Bfr[bsp][kt][nt].y);
                }
            }
        }
    }

    __syncthreads();
    float* sEpi = (float*)sAct;   // 128*33*4 = 16896 B <= 20800 B
#pragma unroll
    for (int mt = 0; mt < 2; mt++)
#pragma unroll
        for (int nt = 0; nt < 4; nt++) {
            int r = wid * 32 + mt * 16 + (lane >> 2);
            int c = nt * 8 + (lane & 3) * 2;
            sEpi[r * 33 + c]           = acc[mt][nt][0];
            sEpi[r * 33 + c + 1]       = acc[mt][nt][1];
            sEpi[(r + 8) * 33 + c]     = acc[mt][nt][2];
            sEpi[(r + 8) * 33 + c + 1] = acc[mt][nt][3];
        }
    __syncthreads();

    if (tid < 104) {
        int w = w0 + tid;
#pragma unroll
        for (int oc = 0; oc < 32; oc++) {
            long long idx = ((long long)(oc * DD + d) * HH + h) * WW + w;
            float val = sEpi[tid * 33 + oc] + sBias[oc] + xres[idx];
            out[idx] = fmaxf(val, 0.f);
        }
    }
}

// ---------- launcher ----------
extern "C" void kernel_launch(void* const* d_in, const int* in_sizes, int n_in,
                              void* d_out, int out_size) {
    const float* x  = (const float*)d_in[0];
    const float* g  = (const float*)d_in[1];
    const float* cw = (const float*)d_in[2];
    const float* g1 = (const float*)d_in[3];
    const float* b1 = (const float*)d_in[4];
    const float* m1 = (const float*)d_in[5];
    const float* v1 = (const float*)d_in[6];
    const float* g2 = (const float*)d_in[7];
    const float* b2 = (const float*)d_in[8];
    const float* m2 = (const float*)d_in[9];
    const float* v2 = (const float*)d_in[10];
    float* out = (float*)d_out;

    k_norm<<<(4 * HW + 255) / 256, 256>>>(g);
    k_wfrag<<<(2 * 27 * 512 + 255) / 256, 256>>>(cw, g1, b1, m1, v1, g2, b2, m2, v2);
    k_transpose<<<DD * HH, 256>>>(x);
    k_scan<<<4352, 32>>>();
    k_combine<<<(NELEM / 4 + 255) / 256, 256>>>();
    k_mma<<<dim3(HH, DD, 2), 128>>>(x, out);
}

// round 13
// speedup vs baseline: 1.6269x; 1.6269x over previous
#include <cuda_runtime.h>
#include <cuda_bf16.h>
#include <cuda_fp16.h>
#include <cstdint>
#include <cstring>

#define CC 32
#define DD 48
#define HH 64
#define WW 208
#define HW 13312            // HH*WW
#define NELEM (CC*DD*HH*WW) // 20447232
#define CEPS 1e-5f
#define NEGINF -3.402823e38f

typedef unsigned long long ull;

// ---------- scratch (device globals: allocation-free) ----------
__device__ float g_kn[4 * 5 * HW];        // normalized guidance
__device__ float g_xt[NELEM];             // x transposed [d][h][w][c]
__device__ float g_accA[NELEM];           // W fwd
__device__ float g_accB[NELEM];           // W bwd
__device__ float g_accC[NELEM];           // H fwd
__device__ float g_accD[NELEM];           // H bwd
__device__ __half g_ah[NELEM];            // activation fp16 [d][h][w][c]
__device__ uint32_t g_wfrag[2 * 27 * 512]; // B fragments fp16 [sp][tap][kt][nt][lane][reg]
__device__ float g_bias2[32];
__device__ float g_s1v[32];
__device__ float g_b1v[32];

// ---------- helpers ----------
__device__ __forceinline__ uint32_t smem_u32(const void* p) {
    uint32_t a;
    asm("{ .reg .u64 t; cvta.to.shared.u64 t, %1; cvt.u32.u64 %0, t; }" : "=r"(a) : "l"(p));
    return a;
}
__device__ __forceinline__ void ldm4(uint32_t* r, uint32_t addr) {
    asm volatile("ldmatrix.sync.aligned.m8n8.x4.shared.b16 {%0,%1,%2,%3}, [%4];"
                 : "=r"(r[0]), "=r"(r[1]), "=r"(r[2]), "=r"(r[3]) : "r"(addr));
}
__device__ __forceinline__ void mma16816h(float* c, const uint32_t* a, uint32_t b0, uint32_t b1) {
    asm volatile("mma.sync.aligned.m16n8k16.row.col.f32.f16.f16.f32 "
                 "{%0,%1,%2,%3}, {%4,%5,%6,%7}, {%8,%9}, {%0,%1,%2,%3};"
                 : "+f"(c[0]), "+f"(c[1]), "+f"(c[2]), "+f"(c[3])
                 : "r"(a[0]), "r"(a[1]), "r"(a[2]), "r"(a[3]), "r"(b0), "r"(b1));
}
__device__ __forceinline__ unsigned short h16bits(__half v) {
    unsigned short s;
    memcpy(&s, &v, 2);
    return s;
}
__device__ __forceinline__ void cpasync16(uint32_t d, const void* s, bool valid) {
    int sz = valid ? 16 : 0;
    asm volatile("cp.async.cg.shared.global [%0], [%1], 16, %2;"
                 :: "r"(d), "l"(s), "r"(sz) : "memory");
}
__device__ __forceinline__ void cpasync_commit_wait() {
    asm volatile("cp.async.commit_group;" ::: "memory");
    asm volatile("cp.async.wait_group 0;" ::: "memory");
}

// ---------- 1) guidance L1 normalization ----------
__global__ void k_norm(const float* __restrict__ g) {
    int i = blockIdx.x * blockDim.x + threadIdx.x;
    if (i >= 4 * HW) return;
    int dir = i / HW;
    int hw  = i % HW;
    float v[5];
    float s = 0.f;
#pragma unroll
    for (int j = 0; j < 5; j++) {
        v[j] = g[(5 * dir + j) * HW + hw];
        s += fabsf(v[j]);
    }
    float inv = 1.f / fmaxf(s, 1e-12f);
#pragma unroll
    for (int j = 0; j < 5; j++)
        g_kn[(dir * 5 + j) * HW + hw] = v[j] * inv;
}

// ---------- 2) transpose NCDHW -> [d][h][w][c] ----------
__global__ void k_transpose(const float* __restrict__ x) {
    __shared__ float t[32][209];
    int d = blockIdx.x / HH;
    int h = blockIdx.x % HH;
    for (int i = threadIdx.x; i < 32 * WW; i += blockDim.x) {
        int c = i / WW, w = i % WW;
        t[c][w] = x[((c * DD + d) * HH + h) * WW + w];
    }
    __syncthreads();
    float* dst = g_xt + (d * HH + h) * WW * 32;
    for (int i = threadIdx.x; i < WW * 32; i += blockDim.x) {
        dst[i] = t[i & 31][i >> 5];
    }
}

// ---------- 3) prep: BN params + fp16-split B fragments in mma frag order ----------
// weights split to fp16 hi+lo (effectively exact); activations will be single fp16.
__global__ void k_wfrag(const float* __restrict__ cw,
                        const float* __restrict__ g1, const float* __restrict__ b1,
                        const float* __restrict__ m1, const float* __restrict__ v1,
                        const float* __restrict__ g2, const float* __restrict__ b2,
                        const float* __restrict__ m2, const float* __restrict__ v2) {
    int i = blockIdx.x * blockDim.x + threadIdx.x;
    if (i < 2 * 27 * 512) {
        int reg  = i & 1;
        int lane = (i >> 1) & 31;
        int nt   = (i >> 6) & 3;
        int kt   = (i >> 8) & 1;
        int rest = i >> 9;
        int tap  = rest % 27;
        int sp   = rest / 27;
        int oc   = nt * 8 + (lane >> 2);
        int icb  = kt * 16 + (lane & 3) * 2 + reg * 8;
        float s2 = g2[oc] * rsqrtf(v2[oc] + CEPS);
        uint32_t pack = 0;
#pragma unroll
        for (int e = 0; e < 2; e++) {
            int ic = icb + e;
            float wv = cw[(oc * 32 + ic) * 27 + tap] * s2;
            __half wh = __float2half(wv);
            __half val = sp ? __float2half(wv - __half2float(wh)) : wh;
            pack |= (uint32_t)h16bits(val) << (16 * e);
        }
        g_wfrag[i] = pack;
    }
    if (i < 32) {
        float s2 = g2[i] * rsqrtf(v2[i] + CEPS);
        g_bias2[i] = b2[i] - m2[i] * s2;
        float s1 = g1[i] * rsqrtf(v1[i] + CEPS);
        g_s1v[i] = s1;
        g_b1v[i] = b1[i] - m1[i] * s1;
    }
}

// ---------- 4) fused 4-direction scan (R6 config: 2176 warps, 8ch/lane; 182us measured) ----------
__global__ void __launch_bounds__(32) k_scan() {
    int lane = threadIdx.x;
    int ds = lane >> 3;
    int cl = lane & 7;
    int bx = blockIdx.x;

    int nsteps, pitch, p0;
    const float* kb; float* ob; int kpitch;
    int cg;
    int planeIdx0;
    if (bx < 512) {
        int h = bx & 63;
        int dir = (bx >> 6) & 1;
        cg = bx >> 7;
        nsteps = WW;
        kb = g_kn + dir * 5 * HW + h * WW;
        ob = dir ? g_accB : g_accA;
        int ps = dir ? -1 : 1;
        p0 = dir ? (WW - 1) : 0;
        pitch = ps;
        kpitch = ps;
        planeIdx0 = h * WW + p0;
    } else {
        int i = bx - 512;
        int w = i % 208;
        int r = i / 208;
        int dir = r & 1;
        cg = r >> 1;
        nsteps = HH;
        kb = g_kn + (2 + dir) * 5 * HW + w;
        ob = dir ? g_accD : g_accC;
        int hs = dir ? -1 : 1;
        int h0 = dir ? (HH - 1) : 0;
        pitch = hs * WW;
        kpitch = hs * WW;
        planeIdx0 = h0 * WW + w;
        p0 = h0 * WW;
    }
    int c = cg * 8 + cl;
    int d0 = ds * 12;

    const float* xp = g_xt + ((long long)d0 * HW + planeIdx0) * 32 + c;
    float* op = ob + ((long long)d0 * HW + planeIdx0) * 32 + c;
    const long long DSTR = (long long)HW * 32;
    const long long PSTR = (long long)pitch * 32;
    const float* kp;
    if (bx < 512) kp = kb + ((pitch > 0) ? 0 : (WW - 1));
    else kp = kb + p0;

    float A[12], xv[12], wv[5];
    float lmx = NEGINF;
#pragma unroll
    for (int j = 0; j < 12; j++) {
        xv[j] = xp[j * DSTR];
        A[j] = xv[j];
        lmx = fmaxf(lmx, A[j]);
    }
#pragma unroll
    for (int j = 0; j < 5; j++) wv[j] = kp[j * HW];
    float gmx = fmaxf(lmx, __shfl_xor_sync(0xffffffffu, lmx, 8));
    gmx = fmaxf(gmx, __shfl_xor_sync(0xffffffffu, gmx, 16));

    for (int s = 0; s < nsteps; s++) {
        bool last = (s == nsteps - 1);
        const float* xpn = last ? xp : (xp + PSTR);
        const float* kpn = last ? kp : (kp + kpitch);
        float xn[12], wn[5];
#pragma unroll
        for (int j = 0; j < 12; j++) xn[j] = xpn[j * DSTR];
#pragma unroll
        for (int j = 0; j < 5; j++) wn[j] = kpn[j * HW];

        float fromUp = __shfl_up_sync(0xffffffffu, A[11], 8);
        float fromDn = __shfl_down_sync(0xffffffffu, A[0], 8);
        float up0   = (ds == 0) ? A[0]  : fromUp;
        float dnTop = (ds == 3) ? A[11] : fromDn;
        float w0 = wv[0], w1 = wv[1], w2 = wv[2], w3 = wv[3], w4 = wv[4];
        float prevOld = A[0];
#pragma unroll
        for (int j = 0; j < 12; j++) {
            float old = A[j];
            float up = (j == 0) ? up0 : prevOld;
            float dn = (j == 11) ? dnTop : A[j + 1];
            float nv = w0 * xv[j] + w1 * old + w2 * up + w3 * dn + w4 * gmx;
            op[j * DSTR] = nv;
            A[j] = nv;
            prevOld = old;
        }
        float t0 = fmaxf(A[0], A[1]),  t1 = fmaxf(A[2], A[3]);
        float t2 = fmaxf(A[4], A[5]),  t3 = fmaxf(A[6], A[7]);
        float t4 = fmaxf(A[8], A[9]),  t5 = fmaxf(A[10], A[11]);
        float u0 = fmaxf(t0, t1), u1 = fmaxf(t2, t3), u2 = fmaxf(t4, t5);
        float lm = fmaxf(u0, fmaxf(u1, u2));
        lm = fmaxf(lm, __shfl_xor_sync(0xffffffffu, lm, 8));
        gmx = fmaxf(lm, __shfl_xor_sync(0xffffffffu, lm, 16));

#pragma unroll
        for (int j = 0; j < 12; j++) xv[j] = xn[j];
#pragma unroll
        for (int j = 0; j < 5; j++) wv[j] = wn[j];
        xp = xpn;
        kp = kpn;
        op += PSTR;
    }
}

// ---------- 5) combine: relu(bn1(max4)) -> single fp16 buffer, [d][h][w][c] ----------
__global__ void __launch_bounds__(256) k_combine() {
    __shared__ float s1s[32], b1s[32];
    int tid = threadIdx.x;
    if (tid < 32) { s1s[tid] = g_s1v[tid]; b1s[tid] = g_b1v[tid]; }
    __syncthreads();
    int i = blockIdx.x * 256 + tid;
    if (i >= NELEM / 4) return;
    float4 a = ((const float4*)g_accA)[i];
    float4 b = ((const float4*)g_accB)[i];
    float4 cc = ((const float4*)g_accC)[i];
    float4 dd = ((const float4*)g_accD)[i];
    int c0 = (i * 4) & 31;
    float v[4];
    v[0] = fmaxf(fmaxf(fmaxf(a.x, b.x), fmaxf(cc.x, dd.x)) * s1s[c0 + 0] + b1s[c0 + 0], 0.f);
    v[1] = fmaxf(fmaxf(fmaxf(a.y, b.y), fmaxf(cc.y, dd.y)) * s1s[c0 + 1] + b1s[c0 + 1], 0.f);
    v[2] = fmaxf(fmaxf(fmaxf(a.z, b.z), fmaxf(cc.z, dd.z)) * s1s[c0 + 2] + b1s[c0 + 2], 0.f);
    v[3] = fmaxf(fmaxf(fmaxf(a.w, b.w), fmaxf(cc.w, dd.w)) * s1s[c0 + 3] + b1s[c0 + 3], 0.f);
    uint32_t p0 = (uint32_t)h16bits(__float2half(v[0]))
                | ((uint32_t)h16bits(__float2half(v[1])) << 16);
    uint32_t p1 = (uint32_t)h16bits(__float2half(v[2]))
                | ((uint32_t)h16bits(__float2half(v[3])) << 16);
    ((uint2*)g_ah)[i] = make_uint2(p0, p1);
}

// ---------- 6) conv via warp HMMA fp16: 27 shifted GEMMs, a x (wh + wl) ----------
// CTA = M=128 w-rows (valid 104) x N=32 oc; 4 warps each m32 x n32.
// sAct rows padded to 40 halfs (80B) -> conflict-free ldmatrix.
// B fragments via __ldg (110KB, L1-resident).
#define AROW 40
#define ACT_BYTES (130 * AROW * 2)      // 10400 B
#define EPI_BYTES (128 * 33 * 4)        // 16896 B
__global__ void __launch_bounds__(128) k_mma(const float* __restrict__ xres,
                                             float* __restrict__ out) {
    __shared__ alignas(16) unsigned char sRaw[EPI_BYTES];  // covers act (10400) and epi
    __shared__ float sBias[32];
    __half* sAct = (__half*)sRaw;

    int tid = threadIdx.x;
    int wid = tid >> 5;
    int lane = tid & 31;
    int h = blockIdx.x;
    int d = blockIdx.y;
    int w0 = blockIdx.z * 104;

    if (tid < 32) sBias[tid] = g_bias2[tid];

    uint32_t sact_u = smem_u32(sAct);
    uint32_t lm_lane = (uint32_t)((lane & 15) * (AROW * 2) + (lane >> 4) * 16);

    float acc[2][4][4];
#pragma unroll
    for (int mt = 0; mt < 2; mt++)
#pragma unroll
        for (int nt = 0; nt < 4; nt++)
#pragma unroll
            for (int r = 0; r < 4; r++) acc[mt][nt][r] = 0.f;

#pragma unroll
    for (int kd = 0; kd < 3; kd++) {
        int din = d + kd - 1;
        if ((unsigned)din >= DD) continue;
#pragma unroll
        for (int kh = 0; kh < 3; kh++) {
            int hin = h + kh - 1;
            if ((unsigned)hin >= HH) continue;

            __syncthreads();    // previous phase's reads complete
            // stage activations via cp.async: rows w0-1..w0+128 (130) x 32 fp16
            {
                long long rowb = (long long)(din * HH + hin) * WW;
                for (int c = tid; c < 520; c += 128) {
                    int r = c >> 2, q = c & 3;
                    int w = w0 - 1 + r;
                    bool valid = (unsigned)w < WW;
                    int wc = valid ? w : 0;
                    const __half* gs = g_ah + (rowb + wc) * 32 + q * 8;
                    cpasync16(sact_u + (uint32_t)(r * (AROW * 2) + q * 16), gs, valid);
                }
            }
            cpasync_commit_wait();
            __syncthreads();

            int tap3 = kd * 9 + kh * 3;
#pragma unroll
            for (int kw = 0; kw < 3; kw++) {
                uint32_t Afr[2][2][4];          // [mt][kt][4]
#pragma unroll
                for (int mt = 0; mt < 2; mt++)
#pragma unroll
                    for (int kt = 0; kt < 2; kt++) {
                        uint32_t addr = sact_u + lm_lane
                                      + (uint32_t)((wid * 32 + mt * 16 + kw) * (AROW * 2)
                                                   + kt * 32);
                        ldm4(Afr[mt][kt], addr);
                    }
                uint2 Bfr[2][2][4];             // [bsp][kt][nt]
#pragma unroll
                for (int bsp = 0; bsp < 2; bsp++) {
                    const uint2* wb = (const uint2*)(g_wfrag + (bsp * 27 + tap3 + kw) * 512);
#pragma unroll
                    for (int kt = 0; kt < 2; kt++)
#pragma unroll
                        for (int nt = 0; nt < 4; nt++)
                            Bfr[bsp][kt][nt] = __ldg(&wb[(kt * 4 + nt) * 32 + lane]);
                }
#pragma unroll
                for (int bsp = 0; bsp < 2; bsp++) {     // a*wh + a*wl
#pragma unroll
                    for (int mt = 0; mt < 2; mt++)
#pragma unroll
                        for (int nt = 0; nt < 4; nt++)
#pragma unroll
                            for (int kt = 0; kt < 2; kt++)
                                mma16816h(acc[mt][nt], Afr[mt][kt],
                                          Bfr[bsp][kt][nt].x, Bfr[bsp][kt][nt].y);
                }
            }
        }
    }

    __syncthreads();
    float* sEpi = (float*)sRaw;
#pragma unroll
    for (int mt = 0; mt < 2; mt++)
#pragma unroll
        for (int nt = 0; nt < 4; nt++) {
            int r = wid * 32 + mt * 16 + (lane >> 2);
            int c = nt * 8 + (lane & 3) * 2;
            sEpi[r * 33 + c]           = acc[mt][nt][0];
            sEpi[r * 33 + c + 1]       = acc[mt][nt][1];
            sEpi[(r + 8) * 33 + c]     = acc[mt][nt][2];
            sEpi[(r + 8) * 33 + c + 1] = acc[mt][nt][3];
        }
    __syncthreads();

    if (tid < 104) {
        int w = w0 + tid;
#pragma unroll
        for (int oc = 0; oc < 32; oc++) {
            long long idx = ((long long)(oc * DD + d) * HH + h) * WW + w;
            float val = sEpi[tid * 33 + oc] + sBias[oc] + xres[idx];
            out[idx] = fmaxf(val, 0.f);
        }
    }
}

// ---------- launcher ----------
extern "C" void kernel_launch(void* const* d_in, const int* in_sizes, int n_in,
                              void* d_out, int out_size) {
    const float* x  = (const float*)d_in[0];
    const float* g  = (const float*)d_in[1];
    const float* cw = (const float*)d_in[2];
    const float* g1 = (const float*)d_in[3];
    const float* b1 = (const float*)d_in[4];
    const float* m1 = (const float*)d_in[5];
    const float* v1 = (const float*)d_in[6];
    const float* g2 = (const float*)d_in[7];
    const float* b2 = (const float*)d_in[8];
    const float* m2 = (const float*)d_in[9];
    const float* v2 = (const float*)d_in[10];
    float* out = (float*)d_out;

    k_norm<<<(4 * HW + 255) / 256, 256>>>(g);
    k_wfrag<<<(2 * 27 * 512 + 255) / 256, 256>>>(cw, g1, b1, m1, v1, g2, b2, m2, v2);
    k_transpose<<<DD * HH, 256>>>(x);
    k_scan<<<2176, 32>>>();
    k_combine<<<(NELEM / 4 + 255) / 256, 256>>>();
    k_mma<<<dim3(HH, DD, 2), 128>>>(x, out);
}